// round 1
// baseline (speedup 1.0000x reference)
#include <cuda_runtime.h>
#include <math.h>

// Problem constants: B=64, I=2048, N=16 (in_dim), J=16 (num_caps), M=16 (dim)
#define B_  64
#define I_  2048
#define N_  16
#define J_  16
#define M_  16
#define JM  256        // J*M
#define NUM_ROUTING 3

// Scratch (device globals — allocation-free per harness rules)
__device__ float g_uhat[(size_t)B_ * I_ * JM];   // 134 MB: u_hat[b][i][j][m]
__device__ float g_s[B_ * JM];                   // s accumulator [b][j][m]
__device__ float g_osum[B_ * JM];                // sum of previous squashed outputs

// ---------------------------------------------------------------------------
// Zero the small accumulators
__global__ void k_zero() {
    int t = blockIdx.x * blockDim.x + threadIdx.x;
    if (t < B_ * JM) { g_s[t] = 0.f; g_osum[t] = 0.f; }
}

// ---------------------------------------------------------------------------
// K1: u_hat[b,i,j,m] = sum_n inputs[b,i,n] * W[i,j,n,m]
// grid = I_ (one CTA per input capsule i), block = 256 (thread = (j,m))
__global__ void __launch_bounds__(256) k_uhat(const float* __restrict__ inp,
                                              const float* __restrict__ W) {
    const int i = blockIdx.x;
    const int t = threadIdx.x;
    __shared__ float Ws[J_ * N_ * M_];   // 4096 floats (16 KB): W[i][j][n][m]
    __shared__ float Xs[B_ * N_];        // 1024 floats (4 KB):  inputs[b][i][n]

    const float* Wp = W + (size_t)i * (J_ * N_ * M_);
    #pragma unroll
    for (int k = t; k < J_ * N_ * M_; k += 256) Ws[k] = Wp[k];
    for (int k = t; k < B_ * N_; k += 256) {
        int b = k >> 4, n = k & 15;
        Xs[k] = inp[((size_t)b * I_ + i) * N_ + n];
    }
    __syncthreads();

    const int j = t >> 4, m = t & 15;
    // hoist this thread's W column into registers: w[n] = W[i][j][n][m]
    float w[N_];
    #pragma unroll
    for (int n = 0; n < N_; n++) w[n] = Ws[j * (N_ * M_) + n * M_ + m];

    #pragma unroll 4
    for (int b = 0; b < B_; b++) {
        const float4* X4 = (const float4*)(Xs + b * N_);
        float4 x0 = X4[0], x1 = X4[1], x2 = X4[2], x3 = X4[3];
        float acc = x0.x * w[0]  + x0.y * w[1]  + x0.z * w[2]  + x0.w * w[3];
        acc      += x1.x * w[4]  + x1.y * w[5]  + x1.z * w[6]  + x1.w * w[7];
        acc      += x2.x * w[8]  + x2.y * w[9]  + x2.z * w[10] + x2.w * w[11];
        acc      += x3.x * w[12] + x3.y * w[13] + x3.z * w[14] + x3.w * w[15];
        g_uhat[((size_t)b * I_ + i) * JM + t] = acc;   // 256 consecutive floats
    }
}

// ---------------------------------------------------------------------------
// K3: one routing pass.  logits[b,i,j] = dot_m(osum[b,j,:], u_hat[b,i,j,:])
//     c = softmax_j(logits);  s[b,j,m] += sum_i c * u_hat[b,i,j,m]
// grid = (B_, CHUNKS), block = 256 (8 warps, each warp owns IW consecutive i)
#define WARPS_PER_CTA 8
#define CHUNKS 32
#define IW (I_ / (CHUNKS * WARPS_PER_CTA))   // = 8
__global__ void __launch_bounds__(256) k_route() {
    const int b     = blockIdx.x;
    const int chunk = blockIdx.y;
    const int wid   = threadIdx.x >> 5;
    const int lane  = threadIdx.x & 31;

    __shared__ float os[JM];
    __shared__ float ss[JM];
    os[threadIdx.x] = g_osum[b * JM + threadIdx.x];
    ss[threadIdx.x] = 0.f;
    __syncthreads();

    // lane l owns u[j][mbase..mbase+7] with j = l/2, mbase = (l&1)*8
    const int j     = lane >> 1;
    const int mbase = (lane & 1) * 8;
    float o[8];
    #pragma unroll
    for (int k = 0; k < 8; k++) o[k] = os[j * M_ + mbase + k];

    float acc[8];
    #pragma unroll
    for (int k = 0; k < 8; k++) acc[k] = 0.f;

    const int i0 = (chunk * WARPS_PER_CTA + wid) * IW;
    for (int ii = 0; ii < IW; ii++) {
        const int i = i0 + ii;
        const float4* up = ((const float4*)g_uhat) + ((size_t)b * I_ + i) * (JM / 4);
        float4 u0 = up[lane * 2], u1 = up[lane * 2 + 1];
        float u[8] = {u0.x, u0.y, u0.z, u0.w, u1.x, u1.y, u1.z, u1.w};

        // partial dot over this lane's 8 m's, combine with pair lane -> full dot
        float p = u[0]*o[0] + u[1]*o[1] + u[2]*o[2] + u[3]*o[3]
                + u[4]*o[4] + u[5]*o[5] + u[6]*o[6] + u[7]*o[7];
        p += __shfl_xor_sync(0xffffffffu, p, 1);   // logit[j], in both pair lanes

        // softmax over the 16 distinct j's: butterfly over same-parity lanes
        float mx = p;
        #pragma unroll
        for (int off = 2; off < 32; off <<= 1)
            mx = fmaxf(mx, __shfl_xor_sync(0xffffffffu, mx, off));
        float e = __expf(p - mx);
        float sum = e;
        #pragma unroll
        for (int off = 2; off < 32; off <<= 1)
            sum += __shfl_xor_sync(0xffffffffu, sum, off);
        float c = e / sum;

        #pragma unroll
        for (int k = 0; k < 8; k++) acc[k] += c * u[k];
    }

    // stage per-warp partials in smem, then one global atomic set per CTA
    float* sp = ss + j * M_ + mbase;
    #pragma unroll
    for (int k = 0; k < 8; k++) atomicAdd(sp + k, acc[k]);
    __syncthreads();
    atomicAdd(&g_s[b * JM + threadIdx.x], ss[threadIdx.x]);
}

// ---------------------------------------------------------------------------
// K2: outputs = squash(s); mode 0: osum += outputs, s = 0; mode 1: write d_out
__global__ void __launch_bounds__(256) k_squash(float* __restrict__ out, int mode) {
    const int b = blockIdx.x;
    const int t = threadIdx.x;            // t = j*16 + m
    float s = g_s[b * JM + t];
    float n2 = s * s;
    #pragma unroll
    for (int off = 1; off < 16; off <<= 1)   // reduce over m (16-lane groups)
        n2 += __shfl_xor_sync(0xffffffffu, n2, off);
    float scale = n2 / (1.f + n2) * rsqrtf(n2 + 1e-8f);
    float v = scale * s;
    if (mode == 0) {
        g_osum[b * JM + t] += v;
        g_s[b * JM + t] = 0.f;
    } else {
        out[b * JM + t] = v;
    }
}

// ---------------------------------------------------------------------------
extern "C" void kernel_launch(void* const* d_in, const int* in_sizes, int n_in,
                              void* d_out, int out_size) {
    const float* inp = (const float*)d_in[0];   // [B, I, N]
    const float* W   = (const float*)d_in[1];   // [I, J, N, M]
    float* out = (float*)d_out;                 // [B, J, M]

    k_zero<<<(B_ * JM + 255) / 256, 256>>>();
    k_uhat<<<I_, 256>>>(inp, W);

    dim3 rgrid(B_, CHUNKS);
    // iter 0 (osum = 0 -> uniform softmax)
    k_route<<<rgrid, 256>>>();
    k_squash<<<B_, 256>>>(out, 0);
    // iter 1
    k_route<<<rgrid, 256>>>();
    k_squash<<<B_, 256>>>(out, 0);
    // iter 2 (final)
    k_route<<<rgrid, 256>>>();
    k_squash<<<B_, 256>>>(out, 1);
}